// round 13
// baseline (speedup 1.0000x reference)
#include <cuda_runtime.h>
#include <cuda_bf16.h>
#include <mma.h>
#include <cstdint>

#define CG 16
#define HW 4096
#define NG 512

typedef unsigned long long ull;
using namespace nvcuda;

__device__ __nv_bfloat16 g_x3[(size_t)NG * CG * HW];
__device__ float g_ah[NG * CG * 64];
__device__ float g_aw[NG * CG * 64];
__device__ float g_cs[NG * CG * 2];            // max3, V3

__device__ __forceinline__ float wsum(float v){
  #pragma unroll
  for (int o = 16; o; o >>= 1) v += __shfl_xor_sync(0xffffffffu, v, o);
  return v;
}
__device__ __forceinline__ float wmax(float v){
  #pragma unroll
  for (int o = 16; o; o >>= 1) v = fmaxf(v, __shfl_xor_sync(0xffffffffu, v, o));
  return v;
}
__device__ __forceinline__ float wmin(float v){
  #pragma unroll
  for (int o = 16; o; o >>= 1) v = fminf(v, __shfl_xor_sync(0xffffffffu, v, o));
  return v;
}

// ---- KA dynamic smem layout (byte offsets after 1024-alignment) ------------
// A:    0     .. 49152   384 rows x 64 bf16 (128B rows), m = t0-64+a
// B:    49152 .. 55296   3 x [16 oc x 64 k] bf16 col-major views (ldb=64)
// STG:  55296 .. 71680   16 warps x 16x16 fp32 stage
// RS:   71680 .. 75776   [16][64] fp32 row sums
// Overlay after tile loop (inside A): xw@0, y@4096, W@12288, bb@15360
#define OFF_A   0
#define OFF_B   49152
#define OFF_STG 55296
#define OFF_RS  71680
#define KA_DYN  (75776 + 1024)

__global__ void __launch_bounds__(512, 2) ka_kernel(
    const float* __restrict__ x,
    const float* __restrict__ w1, const float* __restrict__ b1,
    const float* __restrict__ wh, const float* __restrict__ bh,
    const float* __restrict__ ww, const float* __restrict__ bw,
    const float* __restrict__ w3, const float* __restrict__ b3)
{
  extern __shared__ char dynraw[];
  char* dynb = (char*)(((uintptr_t)dynraw + 1023) & ~(uintptr_t)1023);
  __nv_bfloat16* Abuf = (__nv_bfloat16*)(dynb + OFF_A);
  __nv_bfloat16* Bbuf = (__nv_bfloat16*)(dynb + OFF_B);
  float* stage = (float*)(dynb + OFF_STG);
  float* s_rs  = (float*)(dynb + OFF_RS);
  float* s_xw  = (float*)(dynb + 0);       // overlay (post-loop)
  float* s_y   = (float*)(dynb + 4096);
  float* s_W   = (float*)(dynb + 12288);
  float* s_bb  = (float*)(dynb + 15360);

  __shared__ float s_b3[16], schmax3[16], schsum3[16];

  const int t = threadIdx.x, warp = t >> 5, lane = t & 31;
  const int g = blockIdx.x;
  const float* xg = x + (size_t)g * CG * HW;

  if (t < 16) { s_b3[t] = b3[t]; schmax3[t] = 0.f; schsum3[t] = 0.f; }
  // B: [dr][oc rows 64 wide], element (k, oc) at Bbuf[dr*1024 + oc*64 + k]
  for (int i = t; i < 3072; i += 512) {
    int dr = i >> 10, rem = i & 1023, oc = rem >> 6, k = rem & 63;
    float v = 0.f;
    if (k < 48) {
      int dc = k >> 4, ci = k & 15;
      v = w3[((oc * 16 + ci) * 3 + dr) * 3 + dc];
    }
    Bbuf[dr * 1024 + oc * 64 + k] = __float2bfloat16(v);
  }
  // zero A K-pad (k = 48..63), written once, never touched again
  if (t < 384) {
    uint4 z = make_uint4(0, 0, 0, 0);
    *(uint4*)(Abuf + t * 64 + 48) = z;
    *(uint4*)(Abuf + t * 64 + 56) = z;
  }

  // ---- exact fp32 row/col sums (warp == channel, coalesced) ----
  float4 csum4 = make_float4(0.f, 0.f, 0.f, 0.f);
  {
    const float* xc = xg + warp * HW;
    #pragma unroll 4
    for (int it = 0; it < 32; it++) {
      float4 v = *(const float4*)(xc + it * 128 + lane * 4);
      csum4.x += v.x; csum4.y += v.y; csum4.z += v.z; csum4.w += v.w;
      float rs = (v.x + v.y) + (v.z + v.w);
      #pragma unroll
      for (int o = 1; o < 16; o <<= 1) rs += __shfl_xor_sync(0xffffffffu, rs, o);
      if ((lane & 15) == 0) s_rs[warp * 64 + it * 2 + (lane >> 4)] = rs;
    }
  }
  __syncthreads();

  // ---- tile loop: 16 iterations of 256 px ----
  const int joc = lane & 15, half = lane >> 4;
  float s3l = 0.f, m3l = 0.f;            // per-lane stats for oc = joc
  const __nv_bfloat16 HZ = __float2bfloat16(0.f);

  #pragma unroll 1
  for (int s = 0; s < 16; s++) {
    const int t0 = s * 256;
    // scatter-convert: tasks (ci, pi), p = t0-65+pi, slot a = pi-dc, k = dc*16+ci
    #pragma unroll 1
    for (int step = 0; step < 13; step++) {
      int task = t + step * 512;
      if (task < 6176) {
        int ci = task / 386;
        int pi = task - ci * 386;
        int p = t0 - 65 + pi;
        bool pv = (unsigned)p < 4096u;
        float v = pv ? __ldg(xg + ci * HW + p) : 0.f;
        int colp = p & 63;
        __nv_bfloat16 hv = __float2bfloat16(v);
        // dc = 0 (left tap of m=p+1): zero when colp==63 (or p invalid)
        int a0 = pi;
        if (a0 < 384) Abuf[a0 * 64 + ci] = (pv && colp != 63) ? hv : HZ;
        // dc = 1 (center, m=p)
        int a1 = pi - 1;
        if ((unsigned)a1 < 384u) Abuf[a1 * 64 + 16 + ci] = pv ? hv : HZ;
        // dc = 2 (right tap of m=p-1): zero when colp==0 (or p invalid)
        int a2 = pi - 2;
        if ((unsigned)a2 < 384u) Abuf[a2 * 64 + 32 + ci] = (pv && colp != 0) ? hv : HZ;
      }
    }
    __syncthreads();

    // each warp: 16 px x 16 oc output tile via 12 HMMA
    {
      const int a0 = 64 + warp * 16;
      wmma::fragment<wmma::accumulator, 16, 16, 16, float> acc;
      wmma::fill_fragment(acc, 0.f);
      #pragma unroll
      for (int dr = 0; dr < 3; dr++) {
        const __nv_bfloat16* Av = Abuf + (a0 + (dr - 1) * 64) * 64;
        const __nv_bfloat16* Bv = Bbuf + dr * 1024;
        #pragma unroll
        for (int kc = 0; kc < 4; kc++) {
          wmma::fragment<wmma::matrix_a, 16, 16, 16, __nv_bfloat16, wmma::row_major> af;
          wmma::fragment<wmma::matrix_b, 16, 16, 16, __nv_bfloat16, wmma::col_major> bf;
          wmma::load_matrix_sync(af, Av + kc * 16, 64);
          wmma::load_matrix_sync(bf, Bv + kc * 16, 64);
          wmma::mma_sync(acc, af, bf, acc);
        }
      }
      wmma::store_matrix_sync(stage + warp * 256, acc, 16, wmma::mem_row_major);
      __syncwarp();

      // bias + relu + stats + bf16 store (lane = (oc joc, px-half))
      const int m0 = t0 + warp * 16;
      float bz = s_b3[joc];
      const float* st = stage + warp * 256 + half * 8 * 16 + joc;
      uint32_t pk[4];
      #pragma unroll
      for (int q = 0; q < 4; q++) {
        float v0 = fmaxf(st[(2 * q) * 16] + bz, 0.f);
        float v1 = fmaxf(st[(2 * q + 1) * 16] + bz, 0.f);
        s3l += v0 + v1;
        m3l = fmaxf(m3l, fmaxf(v0, v1));
        __nv_bfloat162 h = __floats2bfloat162_rn(v0, v1);
        pk[q] = *(uint32_t*)&h;
      }
      __nv_bfloat16* op = g_x3 + ((size_t)g * CG + joc) * HW + m0 + half * 8;
      *(uint4*)op = make_uint4(pk[0], pk[1], pk[2], pk[3]);
    }
    __syncthreads();
  }

  // ---- fold x3 stats ----
  s3l += __shfl_xor_sync(0xffffffffu, s3l, 16);
  m3l = fmaxf(m3l, __shfl_xor_sync(0xffffffffu, m3l, 16));
  if (half == 0) {
    atomicAdd(&schsum3[joc], s3l);
    atomicMax((int*)&schmax3[joc], __float_as_int(m3l));  // relu >= 0
  }

  // ---- end phase (A region overlay now safe) ----
  csum4.x += __shfl_xor_sync(0xffffffffu, csum4.x, 16);
  csum4.y += __shfl_xor_sync(0xffffffffu, csum4.y, 16);
  csum4.z += __shfl_xor_sync(0xffffffffu, csum4.z, 16);
  csum4.w += __shfl_xor_sync(0xffffffffu, csum4.w, 16);
  if (lane < 16) {
    float* d = s_xw + warp * 64 + lane * 4;
    d[0] = csum4.x; d[1] = csum4.y; d[2] = csum4.z; d[3] = csum4.w;
  }
  if (t < 256) { s_W[t] = w1[t]; s_W[256 + t] = wh[t]; s_W[512 + t] = ww[t]; }
  if (t < 16) { s_bb[t] = b1[t]; s_bb[16 + t] = bh[t]; s_bb[32 + t] = bw[t]; }
  __syncthreads();

  if (t < 16) {
    float* cs = g_cs + (g * CG + t) * 2;
    cs[0] = schmax3[t];
    cs[1] = schsum3[t] * (1.f / 4096.f);
  }
  if (t < 128) {
    float in[16];
    #pragma unroll
    for (int i = 0; i < 16; i++) {
      float raw = (t < 64) ? s_rs[i * 64 + t] : s_xw[i * 64 + (t - 64)];
      in[i] = raw * (1.f / 64.f);
    }
    #pragma unroll
    for (int o = 0; o < 16; o++) {
      float acc = s_bb[o];
      #pragma unroll
      for (int i = 0; i < 16; i++) acc = fmaf(s_W[o * 16 + i], in[i], acc);
      s_y[o * 128 + t] = fmaxf(acc, 0.f);
    }
  }
  __syncthreads();
  if (t < 128) {
    const int hf = t >> 6, cc = t & 63;
    const float* Wm = s_W + 256 + hf * 256;
    const float* bm = s_bb + 16 + hf * 16;
    float in[16];
    #pragma unroll
    for (int i = 0; i < 16; i++) in[i] = s_y[i * 128 + t];
    float* gdst = hf ? (g_aw + g * 1024) : (g_ah + g * 1024);
    #pragma unroll
    for (int o = 0; o < 16; o++) {
      float acc = bm[o];
      #pragma unroll
      for (int i = 0; i < 16; i++) acc = fmaf(Wm[o * 16 + i], in[i], acc);
      gdst[o * 64 + cc] = 1.f / (1.f + __expf(-acc));
    }
  }
}

// ---------------------------------------------------------------------------
// KB: unchanged 149us configuration.
__global__ void __launch_bounds__(512) kb_kernel(const float* __restrict__ x,
                                                 const float* __restrict__ gnw,
                                                 const float* __restrict__ gnb,
                                                 float* __restrict__ out)
{
  __shared__ float s_s[4096];
  __shared__ float s_ah[1024], s_aw[1024];
  __shared__ float s_k[16], s_e2[16], s_m3[16], s_w2[16], s_w3[16];
  __shared__ float schsum1[16], schsq1[16], schmax1[16], schmin1[16];
  __shared__ float s_r1[16];
  __shared__ float s_mu, s_rsd, s_smax, s_sinv;

  const int t = threadIdx.x, warp = t >> 5, lane = t & 31;
  const int g = blockIdx.x;
  const float* xg = x + (size_t)g * CG * HW;
  const __nv_bfloat16* x3g = g_x3 + (size_t)g * CG * HW;

  for (int i = t; i < 1024; i += 512) {
    s_ah[i] = g_ah[g * 1024 + i];
    s_aw[i] = g_aw[g * 1024 + i];
  }
  __syncthreads();

  {
    const int c = warp;
    const float* xc = xg + c * HW;
    const float* ahc = s_ah + c * 64;
    float aw0 = s_aw[c * 64 + lane * 2];
    float aw1 = s_aw[c * 64 + lane * 2 + 1];
    float sum = 0.f, sq = 0.f, mx = -1e30f, mn = 1e30f;
    #pragma unroll 4
    for (int m = 0; m < 64; m++) {
      float2 xv = *reinterpret_cast<const float2*>(xc + m * 64 + lane * 2);
      float a = ahc[m];
      float v0 = xv.x * a * aw0;
      float v1 = xv.y * a * aw1;
      sum += v0 + v1; sq += v0 * v0 + v1 * v1;
      mx = fmaxf(mx, fmaxf(v0, v1)); mn = fminf(mn, fminf(v0, v1));
    }
    sum = wsum(sum); sq = wsum(sq); mx = wmax(mx); mn = wmin(mn);
    if (lane == 0) { schsum1[c] = sum; schsq1[c] = sq; schmax1[c] = mx; schmin1[c] = mn; }
  }
  __syncthreads();
  if (t == 0) {
    float a = 0.f, bq = 0.f;
    #pragma unroll
    for (int i = 0; i < 16; i++) { a += schsum1[i]; bq += schsq1[i]; }
    float mu = a * (1.f / 65536.f);
    float var = bq * (1.f / 65536.f) - mu * mu;
    s_mu = mu; s_rsd = rsqrtf(var + 1e-5f);
  }
  __syncthreads();
  if (t < 16) {
    int c = t;
    float k = s_rsd * gnw[c];
    float d = gnb[c] - s_mu * k;
    float mx1 = (k >= 0.f) ? schmax1[c] : schmin1[c];
    float max2 = mx1 * k + d;
    const float* cs = g_cs + (g * CG + c) * 2;
    s_k[c]  = k;
    s_e2[c] = d - max2;
    s_m3[c] = cs[0];
    s_w2[c] = cs[1];
    s_w3[c] = schsum1[c] * (1.f / 4096.f) * k + d;
  }
  __syncthreads();

  {
    const int c = warp;
    float k = s_k[c], e2 = s_e2[c], m3 = s_m3[c];
    const float* xc = xg + c * HW;
    const __nv_bfloat16* x3c = x3g + c * HW;
    const float* ahc = s_ah + c * 64;
    float aw0 = s_aw[c * 64 + lane * 2];
    float aw1 = s_aw[c * 64 + lane * 2 + 1];
    float z2 = 0.f, z3 = 0.f;
    #pragma unroll 4
    for (int m = 0; m < 64; m++) {
      float2 xv = *reinterpret_cast<const float2*>(xc + m * 64 + lane * 2);
      __nv_bfloat162 x3v = *reinterpret_cast<const __nv_bfloat162*>(x3c + m * 64 + lane * 2);
      float a = ahc[m];
      z2 += __expf(fmaf(xv.x * a * aw0, k, e2)) + __expf(fmaf(xv.y * a * aw1, k, e2));
      z3 += __expf(__bfloat162float(x3v.x) - m3) + __expf(__bfloat162float(x3v.y) - m3);
    }
    z2 = wsum(z2); z3 = wsum(z3);
    if (lane == 0) { s_w3[c] = s_w3[c] / z3; s_w2[c] = s_w2[c] / z2; }
  }
  __syncthreads();

  float lmax = -1e30f;
  #pragma unroll 1
  for (int rep = 0; rep < 8; rep++) {
    int l = t + rep * 512;
    int i = l >> 6, j = l & 63;
    float acc = 0.f;
    #pragma unroll
    for (int c = 0; c < 16; c++) {
      float x1 = xg[c * HW + l] * s_ah[c * 64 + i] * s_aw[c * 64 + j];
      acc += s_w2[c] * __expf(fmaf(x1, s_k[c], s_e2[c]));
      acc += s_w3[c] * __expf(__bfloat162float(x3g[c * HW + l]) - s_m3[c]);
    }
    s_s[l] = acc;
    lmax = fmaxf(lmax, acc);
  }
  lmax = wmax(lmax);
  if (lane == 0) s_r1[warp] = lmax;
  __syncthreads();
  if (t == 0) {
    float m = -1e30f;
    #pragma unroll
    for (int i = 0; i < 16; i++) m = fmaxf(m, s_r1[i]);
    s_smax = m;
  }
  __syncthreads();
  float lsum = 0.f;
  {
    float smax = s_smax;
    #pragma unroll 1
    for (int rep = 0; rep < 8; rep++) {
      int l = t + rep * 512;
      float e = __expf(s_s[l] - smax);
      s_s[l] = e;
      lsum += e;
    }
  }
  lsum = wsum(lsum);
  if (lane == 0) s_r1[warp] = lsum;
  __syncthreads();
  if (t == 0) {
    float a = 0.f;
    #pragma unroll
    for (int i = 0; i < 16; i++) a += s_r1[i];
    s_sinv = 1.f / a;
  }
  __syncthreads();

  float* og = out + (size_t)g * CG * HW;
  float sinv = s_sinv;
  #pragma unroll 1
  for (int c = 0; c < 16; c++) {
    #pragma unroll
    for (int rep = 0; rep < 4; rep++) {
      int l0 = (t + rep * 512) * 2;
      float2 xv = *reinterpret_cast<const float2*>(xg + c * HW + l0);
      float2 ov;
      ov.x = xv.x * (s_s[l0] * sinv);
      ov.y = xv.y * (s_s[l0 + 1] * sinv);
      *reinterpret_cast<float2*>(og + c * HW + l0) = ov;
    }
  }
}

// ---------------------------------------------------------------------------
extern "C" void kernel_launch(void* const* d_in, const int* in_sizes, int n_in,
                              void* d_out, int out_size)
{
  const float* x   = (const float*)d_in[0];
  const float* w1  = (const float*)d_in[1];
  const float* b1  = (const float*)d_in[2];
  const float* wh  = (const float*)d_in[3];
  const float* bh  = (const float*)d_in[4];
  const float* ww  = (const float*)d_in[5];
  const float* bw  = (const float*)d_in[6];
  const float* w3  = (const float*)d_in[7];
  const float* b3  = (const float*)d_in[8];
  const float* gnw = (const float*)d_in[9];
  const float* gnb = (const float*)d_in[10];

  cudaFuncSetAttribute(ka_kernel, cudaFuncAttributeMaxDynamicSharedMemorySize, KA_DYN);
  ka_kernel<<<NG, 512, KA_DYN>>>(x, w1, b1, wh, bh, ww, bw, w3, b3);
  kb_kernel<<<NG, 512>>>(x, gnw, gnb, (float*)d_out);
}

// round 14
// speedup vs baseline: 2.2484x; 2.2484x over previous
#include <cuda_runtime.h>
#include <cuda_bf16.h>

#define CG 16
#define HW 4096
#define NG 512            // b*g groups

typedef unsigned long long ull;

// ---------------- scratch ---------------------------------------------------
__device__ __nv_bfloat16 g_x3[(size_t)NG * CG * HW];   // conv3x3 output (relu'd)

// ---------------- warp reduce helpers --------------------------------------
__device__ __forceinline__ float wsum(float v){
  #pragma unroll
  for (int o = 16; o; o >>= 1) v += __shfl_xor_sync(0xffffffffu, v, o);
  return v;
}
__device__ __forceinline__ float wmax(float v){
  #pragma unroll
  for (int o = 16; o; o >>= 1) v = fmaxf(v, __shfl_xor_sync(0xffffffffu, v, o));
  return v;
}
__device__ __forceinline__ float wmin(float v){
  #pragma unroll
  for (int o = 16; o; o >>= 1) v = fminf(v, __shfl_xor_sync(0xffffffffu, v, o));
  return v;
}

// ---------------- packed f32x2 helpers --------------------------------------
__device__ __forceinline__ ull pk2(float lo, float hi){
  ull r;
  asm("mov.b64 %0, {%1, %2};" : "=l"(r) : "f"(lo), "f"(hi));
  return r;
}
__device__ __forceinline__ void fma2(ull& d, ull a, ull b){
  asm("fma.rn.f32x2 %0, %1, %2, %0;" : "+l"(d) : "l"(a), "l"(b));
}
__device__ __forceinline__ float2 upk2(ull v){
  float2 f;
  asm("mov.b64 {%0, %1}, %2;" : "=f"(f.x), "=f"(f.y) : "l"(v));
  return f;
}

// ---------------- cp.async helpers -----------------------------------------
__device__ __forceinline__ void cpa16(float* dst_smem, const float* src, bool valid){
  unsigned sz = valid ? 16u : 0u;
  unsigned d = (unsigned)__cvta_generic_to_shared(dst_smem);
  asm volatile("cp.async.cg.shared.global [%0], [%1], 16, %2;"
               :: "r"(d), "l"(src), "r"(sz) : "memory");
}
__device__ __forceinline__ void cpa_commit(){
  asm volatile("cp.async.commit_group;" ::: "memory");
}
template<int N>
__device__ __forceinline__ void cpa_wait(){
  asm volatile("cp.async.wait_group %0;" :: "n"(N) : "memory");
}

// ---------------- dynamic smem layout (floats) ------------------------------
#define TILE_RP 68
#define TILE_CP (18 * TILE_RP)             // 1224
#define OFF_T   16
#define OFF_W3D (16 + 16 * TILE_CP)        // 19600 (4608 floats, dup pairs)
#define OFF_RS  (OFF_W3D + 4608)           // 24208 (1024 floats row sums)
#define SM_TOTF (OFF_RS + 1024)            // 25232 floats = 100928 B (2 CTA/SM)

// Each warp loads its channel's 18 rows x 16 16B-chunks = 288 chunks, 9/lane.
__device__ __forceinline__ void issue_strip(float* buf, const float* xc16,
                                            int lane, int r0){
  #pragma unroll
  for (int s = 0; s < 9; s++){
    int chunk = lane + s * 32;
    int rr = chunk >> 4;                   // 0..17
    int col = (chunk & 15) * 4;
    int gr = r0 - 1 + rr;
    cpa16(buf + rr * TILE_RP + col, xc16 + gr * 64 + col, (unsigned)gr < 64u);
  }
}

// ============================================================================
// FUSED kernel: conv3x3 + pooling/1x1 gates (KA phase), then groupnorm /
// softmax attention / output (KB phase), one CTA per group.  The group's x
// stays L2-resident between phases; co-resident CTAs drift into different
// phases, mixing FMA-heavy and MUFU/mem-heavy work on each SM.
// ============================================================================
__global__ void __launch_bounds__(512, 2) fused_kernel(
    const float* __restrict__ x,
    const float* __restrict__ w1, const float* __restrict__ b1,
    const float* __restrict__ wh, const float* __restrict__ bh,
    const float* __restrict__ ww, const float* __restrict__ bw,
    const float* __restrict__ w3, const float* __restrict__ b3,
    const float* __restrict__ gnw, const float* __restrict__ gnb,
    float* __restrict__ out)
{
  extern __shared__ float sm[];
  float* tile  = sm + OFF_T;
  float* s_w3d = sm + OFF_W3D;
  float* s_rs  = sm + OFF_RS;         // [16][64] row sums
  // overlays inside tile region (used after last conv sync)
  float* s_xw = sm + OFF_T + 1024;    // [16][64] col sums
  float* s_y  = sm + OFF_T + 2048;    // [16][128]
  float* s_W  = sm + OFF_T + 4096;    // W1(256) Wh(256) Ww(256)
  float* s_bb = sm + OFF_T + 4864;    // b1(16) bh(16) bw(16)
  float* s_s  = sm + OFF_T + 5120;    // [4096] KB logits/exp (after 1x1 done)

  __shared__ float s_b3[16], schmax3[16], schsum3[16];
  __shared__ float s_ah[1024], s_aw[1024];
  __shared__ float s_k[16], s_e2[16], s_m3[16], s_w2[16], s_w3v[16];
  __shared__ float schsum1[16], schsq1[16], schmax1[16], schmin1[16];
  __shared__ float s_r1[16];
  __shared__ float s_mu, s_rsd, s_smax, s_sinv;

  const int t = threadIdx.x, warp = t >> 5, lane = t & 31;
  const int g = blockIdx.x;
  const float* xg = x + (size_t)g * CG * HW;
  const float* xch = xg + warp * HW;   // this warp's channel

  // ---- init: guard, pads, weights ----
  if (t < 16) { sm[t] = 0.f; s_b3[t] = b3[t]; schmax3[t] = 0.f; schsum3[t] = 0.f; }
  if (t < 288) {                              // 16 ch * 18 rows
    float* row = tile + t * TILE_RP;
    row[64] = 0.f; row[65] = 0.f; row[66] = 0.f; row[67] = 0.f;
  }
  for (int i = t; i < 2304; i += 512) {
    float v = w3[i];
    s_w3d[2 * i] = v; s_w3d[2 * i + 1] = v;
  }

  // ======================= KA phase: conv + pooled stats ====================
  float4 csum4 = make_float4(0.f, 0.f, 0.f, 0.f);   // per-lane col partials
  const int ocp = t >> 6, oc0 = ocp * 2, oc1 = oc0 + 1;
  const int ti = t & 63, rr = ti >> 2, cb = ti & 3; // row 0..15, 16-px blk 0..3
  float m30 = 0.f, m31 = 0.f, s30 = 0.f, s31 = 0.f;
  const ull* w3du = reinterpret_cast<const ull*>(s_w3d);
  const int half = lane >> 4, col4 = (lane & 15) * 4;

  #pragma unroll 1
  for (int s = 0; s < 4; s++) {
    const int r0 = s * 16;
    issue_strip(tile + warp * TILE_CP, xch, lane, r0);
    cpa_commit();
    cpa_wait<0>();
    __syncthreads();                 // strip visible to all

    // stats: warp == channel, data rows 1..16
    {
      const float* bch = tile + warp * TILE_CP;
      #pragma unroll
      for (int st = 0; st < 8; st++) {
        int b = 1 + st * 2 + half;
        float4 v = *reinterpret_cast<const float4*>(bch + b * TILE_RP + col4);
        csum4.x += v.x; csum4.y += v.y; csum4.z += v.z; csum4.w += v.w;
        float rs = (v.x + v.y) + (v.z + v.w);
        #pragma unroll
        for (int o = 1; o < 16; o <<= 1) rs += __shfl_xor_sync(0xffffffffu, rs, o);
        if ((lane & 15) == 0) s_rs[warp * 64 + r0 + st * 2 + half] = rs;
      }
    }

    // conv: one (2 outch x 16 px) tile per thread, packed f32x2
    {
      ull Ac0[8], Ac1[8];
      #pragma unroll
      for (int p = 0; p < 8; p++) { Ac0[p] = 0ull; Ac1[p] = 0ull; }
      const float* tb = tile + rr * TILE_RP + cb * 16;
      #pragma unroll 1
      for (int ci = 0; ci < 16; ci++) {
        const float* tcb = tb + ci * TILE_CP;
        const ull* wa = w3du + oc0 * 144 + ci * 9;
        const ull* wb = w3du + oc1 * 144 + ci * 9;
        #pragma unroll
        for (int dr = 0; dr < 3; dr++) {
          const float* base = tcb + dr * TILE_RP;
          const float lft = base[-1];
          const float4 q0 = *reinterpret_cast<const float4*>(base);
          const float4 q1 = *reinterpret_cast<const float4*>(base + 4);
          const float4 q2 = *reinterpret_cast<const float4*>(base + 8);
          const float4 q3 = *reinterpret_cast<const float4*>(base + 12);
          const float rgt = base[16];
          ull E0 = pk2(q0.x, q0.y), E1 = pk2(q0.z, q0.w);
          ull E2 = pk2(q1.x, q1.y), E3 = pk2(q1.z, q1.w);
          ull E4 = pk2(q2.x, q2.y), E5 = pk2(q2.z, q2.w);
          ull E6 = pk2(q3.x, q3.y), E7 = pk2(q3.z, q3.w);
          ull O0 = pk2(lft,  q0.x), O1 = pk2(q0.y, q0.z);
          ull O2 = pk2(q0.w, q1.x), O3 = pk2(q1.y, q1.z);
          ull O4 = pk2(q1.w, q2.x), O5 = pk2(q2.y, q2.z);
          ull O6 = pk2(q2.w, q3.x), O7 = pk2(q3.y, q3.z);
          ull O8 = pk2(q3.w, rgt);
          {
            ull u0 = wa[dr * 3], u1 = wa[dr * 3 + 1], u2 = wa[dr * 3 + 2];
            fma2(Ac0[0], u0, O0); fma2(Ac0[0], u1, E0); fma2(Ac0[0], u2, O1);
            fma2(Ac0[1], u0, O1); fma2(Ac0[1], u1, E1); fma2(Ac0[1], u2, O2);
            fma2(Ac0[2], u0, O2); fma2(Ac0[2], u1, E2); fma2(Ac0[2], u2, O3);
            fma2(Ac0[3], u0, O3); fma2(Ac0[3], u1, E3); fma2(Ac0[3], u2, O4);
            fma2(Ac0[4], u0, O4); fma2(Ac0[4], u1, E4); fma2(Ac0[4], u2, O5);
            fma2(Ac0[5], u0, O5); fma2(Ac0[5], u1, E5); fma2(Ac0[5], u2, O6);
            fma2(Ac0[6], u0, O6); fma2(Ac0[6], u1, E6); fma2(Ac0[6], u2, O7);
            fma2(Ac0[7], u0, O7); fma2(Ac0[7], u1, E7); fma2(Ac0[7], u2, O8);
          }
          {
            ull u0 = wb[dr * 3], u1 = wb[dr * 3 + 1], u2 = wb[dr * 3 + 2];
            fma2(Ac1[0], u0, O0); fma2(Ac1[0], u1, E0); fma2(Ac1[0], u2, O1);
            fma2(Ac1[1], u0, O1); fma2(Ac1[1], u1, E1); fma2(Ac1[1], u2, O2);
            fma2(Ac1[2], u0, O2); fma2(Ac1[2], u1, E2); fma2(Ac1[2], u2, O3);
            fma2(Ac1[3], u0, O3); fma2(Ac1[3], u1, E3); fma2(Ac1[3], u2, O4);
            fma2(Ac1[4], u0, O4); fma2(Ac1[4], u1, E4); fma2(Ac1[4], u2, O5);
            fma2(Ac1[5], u0, O5); fma2(Ac1[5], u1, E5); fma2(Ac1[5], u2, O6);
            fma2(Ac1[6], u0, O6); fma2(Ac1[6], u1, E6); fma2(Ac1[6], u2, O7);
            fma2(Ac1[7], u0, O7); fma2(Ac1[7], u1, E7); fma2(Ac1[7], u2, O8);
          }
        }
      }
      int grow = r0 + rr;
      float bz0 = s_b3[oc0], bz1 = s_b3[oc1];
      __nv_bfloat162 h0[8], h1[8];
      #pragma unroll
      for (int p = 0; p < 8; p++) {
        float2 f0 = upk2(Ac0[p]);
        float2 f1 = upk2(Ac1[p]);
        float a0 = fmaxf(f0.x + bz0, 0.f), a1 = fmaxf(f0.y + bz0, 0.f);
        float b0v = fmaxf(f1.x + bz1, 0.f), b1v = fmaxf(f1.y + bz1, 0.f);
        m30 = fmaxf(m30, fmaxf(a0, a1)); s30 += a0 + a1;
        m31 = fmaxf(m31, fmaxf(b0v, b1v)); s31 += b0v + b1v;
        h0[p] = __floats2bfloat162_rn(a0, a1);
        h1[p] = __floats2bfloat162_rn(b0v, b1v);
      }
      __nv_bfloat16* o0 = g_x3 + ((size_t)g * CG + oc0) * HW + grow * 64 + cb * 16;
      __nv_bfloat16* o1 = g_x3 + ((size_t)g * CG + oc1) * HW + grow * 64 + cb * 16;
      *reinterpret_cast<uint4*>(o0)     = *reinterpret_cast<uint4*>(h0);
      *reinterpret_cast<uint4*>(o0 + 8) = *reinterpret_cast<uint4*>(h0 + 4);
      *reinterpret_cast<uint4*>(o1)     = *reinterpret_cast<uint4*>(h1);
      *reinterpret_cast<uint4*>(o1 + 8) = *reinterpret_cast<uint4*>(h1 + 4);
    }
    __syncthreads();                 // done reading tile before refill
  }

  // ---- fold col sums, x3 stats, 1x1 convs (ah/aw stay in smem) -------------
  csum4.x += __shfl_xor_sync(0xffffffffu, csum4.x, 16);
  csum4.y += __shfl_xor_sync(0xffffffffu, csum4.y, 16);
  csum4.z += __shfl_xor_sync(0xffffffffu, csum4.z, 16);
  csum4.w += __shfl_xor_sync(0xffffffffu, csum4.w, 16);
  if (lane < 16) {
    float* d = s_xw + warp * 64 + lane * 4;
    d[0] = csum4.x; d[1] = csum4.y; d[2] = csum4.z; d[3] = csum4.w;
  }
  if (t < 256) { s_W[t] = w1[t]; s_W[256 + t] = wh[t]; s_W[512 + t] = ww[t]; }
  if (t < 16) { s_bb[t] = b1[t]; s_bb[16 + t] = bh[t]; s_bb[32 + t] = bw[t]; }
  atomicAdd(&schsum3[oc0], s30);
  atomicAdd(&schsum3[oc1], s31);
  atomicMax(reinterpret_cast<int*>(&schmax3[oc0]), __float_as_int(m30)); // relu>=0
  atomicMax(reinterpret_cast<int*>(&schmax3[oc1]), __float_as_int(m31));
  __syncthreads();

  // y = relu(W1 @ [xh;xw] + b1)
  if (t < 128) {
    float in[16];
    #pragma unroll
    for (int i = 0; i < 16; i++) {
      float raw = (t < 64) ? s_rs[i * 64 + t] : s_xw[i * 64 + (t - 64)];
      in[i] = raw * (1.f / 64.f);
    }
    #pragma unroll
    for (int o = 0; o < 16; o++) {
      float acc = s_bb[o];
      #pragma unroll
      for (int i = 0; i < 16; i++) acc = fmaf(s_W[o * 16 + i], in[i], acc);
      s_y[o * 128 + t] = fmaxf(acc, 0.f);
    }
  }
  __syncthreads();
  // a_h, a_w -> smem (no gmem round-trip)
  if (t < 128) {
    const int hf = t >> 6, cc = t & 63;
    const float* Wm = s_W + 256 + hf * 256;
    const float* bm = s_bb + 16 + hf * 16;
    float in[16];
    #pragma unroll
    for (int i = 0; i < 16; i++) in[i] = s_y[i * 128 + t];
    float* dst = hf ? s_aw : s_ah;
    #pragma unroll
    for (int o = 0; o < 16; o++) {
      float acc = bm[o];
      #pragma unroll
      for (int i = 0; i < 16; i++) acc = fmaf(Wm[o * 16 + i], in[i], acc);
      dst[o * 64 + cc] = 1.f / (1.f + __expf(-acc));
    }
  }
  __syncthreads();

  // ======================= KB phase: attention ==============================
  // ---- pass 0: x1 statistics (warp == channel; x is L2-hot) ----
  {
    const int c = warp;
    const float* xc = xg + c * HW;
    const float* ahc = s_ah + c * 64;
    float aw0 = s_aw[c * 64 + lane * 2];
    float aw1 = s_aw[c * 64 + lane * 2 + 1];
    float sum = 0.f, sq = 0.f, mx = -1e30f, mn = 1e30f;
    #pragma unroll 4
    for (int m = 0; m < 64; m++) {
      float2 xv = *reinterpret_cast<const float2*>(xc + m * 64 + lane * 2);
      float a = ahc[m];
      float v0 = xv.x * a * aw0;
      float v1 = xv.y * a * aw1;
      sum += v0 + v1; sq += v0 * v0 + v1 * v1;
      mx = fmaxf(mx, fmaxf(v0, v1)); mn = fminf(mn, fminf(v0, v1));
    }
    sum = wsum(sum); sq = wsum(sq); mx = wmax(mx); mn = wmin(mn);
    if (lane == 0) { schsum1[c] = sum; schsq1[c] = sq; schmax1[c] = mx; schmin1[c] = mn; }
  }
  __syncthreads();
  if (t == 0) {
    float a = 0.f, bq = 0.f;
    #pragma unroll
    for (int i = 0; i < 16; i++) { a += schsum1[i]; bq += schsq1[i]; }
    float mu = a * (1.f / 65536.f);
    float var = bq * (1.f / 65536.f) - mu * mu;
    s_mu = mu; s_rsd = rsqrtf(var + 1e-5f);
  }
  __syncthreads();
  if (t < 16) {
    int c = t;
    float k = s_rsd * gnw[c];
    float d = gnb[c] - s_mu * k;
    float mx1 = (k >= 0.f) ? schmax1[c] : schmin1[c];
    float max2 = mx1 * k + d;
    s_k[c]  = k;
    s_e2[c] = d - max2;
    s_m3[c] = schmax3[c];                            // max3
    s_w2[c] = schsum3[c] * (1.f / 4096.f);           // V3 (÷ Z2 below)
    s_w3v[c] = schsum1[c] * (1.f / 4096.f) * k + d;  // V2 (÷ Z3 below)
  }
  __syncthreads();

  // ---- pass 1: per-channel Z2, Z3 ----
  {
    const int c = warp;
    float k = s_k[c], e2 = s_e2[c], m3 = s_m3[c];
    const float* xc = xg + c * HW;
    const __nv_bfloat16* x3c = g_x3 + ((size_t)g * CG + c) * HW;
    const float* ahc = s_ah + c * 64;
    float aw0 = s_aw[c * 64 + lane * 2];
    float aw1 = s_aw[c * 64 + lane * 2 + 1];
    float z2 = 0.f, z3 = 0.f;
    #pragma unroll 4
    for (int m = 0; m < 64; m++) {
      float2 xv = *reinterpret_cast<const float2*>(xc + m * 64 + lane * 2);
      __nv_bfloat162 x3v = *reinterpret_cast<const __nv_bfloat162*>(x3c + m * 64 + lane * 2);
      float a = ahc[m];
      z2 += __expf(fmaf(xv.x * a * aw0, k, e2)) + __expf(fmaf(xv.y * a * aw1, k, e2));
      z3 += __expf(__bfloat162float(x3v.x) - m3) + __expf(__bfloat162float(x3v.y) - m3);
    }
    z2 = wsum(z2); z3 = wsum(z3);
    if (lane == 0) { s_w3v[c] = s_w3v[c] / z3; s_w2[c] = s_w2[c] / z2; }
  }
  __syncthreads();

  // ---- pass 2: s logits ----
  const __nv_bfloat16* x3g = g_x3 + (size_t)g * CG * HW;
  float lmax = -1e30f;
  #pragma unroll 1
  for (int rep = 0; rep < 8; rep++) {
    int l = t + rep * 512;
    int i = l >> 6, j = l & 63;
    float acc = 0.f;
    #pragma unroll
    for (int c = 0; c < 16; c++) {
      float x1 = xg[c * HW + l] * s_ah[c * 64 + i] * s_aw[c * 64 + j];
      acc += s_w2[c] * __expf(fmaf(x1, s_k[c], s_e2[c]));
      acc += s_w3v[c] * __expf(__bfloat162float(x3g[c * HW + l]) - s_m3[c]);
    }
    s_s[l] = acc;
    lmax = fmaxf(lmax, acc);
  }
  lmax = wmax(lmax);
  if (lane == 0) s_r1[warp] = lmax;
  __syncthreads();
  if (t == 0) {
    float m = -1e30f;
    #pragma unroll
    for (int i = 0; i < 16; i++) m = fmaxf(m, s_r1[i]);
    s_smax = m;
  }
  __syncthreads();
  float lsum = 0.f;
  {
    float smax = s_smax;
    #pragma unroll 1
    for (int rep = 0; rep < 8; rep++) {
      int l = t + rep * 512;
      float e = __expf(s_s[l] - smax);
      s_s[l] = e;                           // store exp once
      lsum += e;
    }
  }
  lsum = wsum(lsum);
  if (lane == 0) s_r1[warp] = lsum;
  __syncthreads();
  if (t == 0) {
    float a = 0.f;
    #pragma unroll
    for (int i = 0; i < 16; i++) a += s_r1[i];
    s_sinv = 1.f / a;
  }
  __syncthreads();

  // ---- pass 3: out = x * (e * sinv) ----
  float* og = out + (size_t)g * CG * HW;
  float sinv = s_sinv;
  #pragma unroll 1
  for (int c = 0; c < 16; c++) {
    #pragma unroll
    for (int rep = 0; rep < 4; rep++) {
      int l0 = (t + rep * 512) * 2;
      float2 xv = *reinterpret_cast<const float2*>(xg + c * HW + l0);
      float2 ov;
      ov.x = xv.x * (s_s[l0] * sinv);
      ov.y = xv.y * (s_s[l0 + 1] * sinv);
      *reinterpret_cast<float2*>(og + c * HW + l0) = ov;
    }
  }
}

// ---------------------------------------------------------------------------
extern "C" void kernel_launch(void* const* d_in, const int* in_sizes, int n_in,
                              void* d_out, int out_size)
{
  const float* x   = (const float*)d_in[0];
  const float* w1  = (const float*)d_in[1];
  const float* b1  = (const float*)d_in[2];
  const float* wh  = (const float*)d_in[3];
  const float* bh  = (const float*)d_in[4];
  const float* ww  = (const float*)d_in[5];
  const float* bw  = (const float*)d_in[6];
  const float* w3  = (const float*)d_in[7];
  const float* b3  = (const float*)d_in[8];
  const float* gnw = (const float*)d_in[9];
  const float* gnb = (const float*)d_in[10];

  cudaFuncSetAttribute(fused_kernel, cudaFuncAttributeMaxDynamicSharedMemorySize,
                       SM_TOTF * (int)sizeof(float));
  fused_kernel<<<NG, 512, SM_TOTF * sizeof(float)>>>(
      x, w1, b1, wh, bh, ww, bw, w3, b3, gnw, gnb, (float*)d_out);
}

// round 17
// speedup vs baseline: 2.7975x; 1.2442x over previous
#include <cuda_runtime.h>
#include <cuda_bf16.h>
#include <cstdint>

#define CG 16
#define HW 4096
#define NG 512            // b*g groups

typedef unsigned long long ull;

// ---------------- scratch ---------------------------------------------------
__device__ __nv_bfloat16 g_x3[(size_t)NG * CG * HW];   // conv3x3 output (relu'd)

// ---------------- warp reduce helpers --------------------------------------
__device__ __forceinline__ float wsum(float v){
  #pragma unroll
  for (int o = 16; o; o >>= 1) v += __shfl_xor_sync(0xffffffffu, v, o);
  return v;
}
__device__ __forceinline__ float wmax(float v){
  #pragma unroll
  for (int o = 16; o; o >>= 1) v = fmaxf(v, __shfl_xor_sync(0xffffffffu, v, o));
  return v;
}
__device__ __forceinline__ float wmin(float v){
  #pragma unroll
  for (int o = 16; o; o >>= 1) v = fminf(v, __shfl_xor_sync(0xffffffffu, v, o));
  return v;
}

// ---------------- packed f32x2 helpers --------------------------------------
__device__ __forceinline__ ull pk2(float lo, float hi){
  ull r;
  asm("mov.b64 %0, {%1, %2};" : "=l"(r) : "f"(lo), "f"(hi));
  return r;
}
__device__ __forceinline__ void fma2(ull& d, ull a, ull b){
  asm("fma.rn.f32x2 %0, %1, %2, %0;" : "+l"(d) : "l"(a), "l"(b));
}
__device__ __forceinline__ float2 upk2(ull v){
  float2 f;
  asm("mov.b64 {%0, %1}, %2;" : "=f"(f.x), "=f"(f.y) : "l"(v));
  return f;
}

// ---------------- cp.async helpers -----------------------------------------
__device__ __forceinline__ void cpa16(float* dst_smem, const float* src, bool valid){
  unsigned sz = valid ? 16u : 0u;
  unsigned d = (unsigned)__cvta_generic_to_shared(dst_smem);
  asm volatile("cp.async.cg.shared.global [%0], [%1], 16, %2;"
               :: "r"(d), "l"(src), "r"(sz) : "memory");
}
__device__ __forceinline__ void cpa_commit(){
  asm volatile("cp.async.commit_group;" ::: "memory");
}
template<int N>
__device__ __forceinline__ void cpa_wait(){
  asm volatile("cp.async.wait_group %0;" :: "n"(N) : "memory");
}

// ---------------- dynamic smem layout (floats) ------------------------------
#define TILE_RP 68
#define TILE_CP (18 * TILE_RP)             // 1224
#define OFF_T   16
#define OFF_W3D (16 + 16 * TILE_CP)        // 19600 (4608 floats, dup pairs)
#define OFF_RS  (OFF_W3D + 4608)           // 24208 (1024 floats row sums)
#define SM_TOTF (OFF_RS + 1024)            // 25232 floats = 100928 B (2 CTA/SM)

// Each warp loads its channel's 18 rows x 16 16B-chunks = 288 chunks, 9/lane.
__device__ __forceinline__ void issue_strip(float* buf, const float* xc16,
                                            int lane, int r0){
  #pragma unroll
  for (int s = 0; s < 9; s++){
    int chunk = lane + s * 32;
    int rr = chunk >> 4;                   // 0..17
    int col = (chunk & 15) * 4;
    int gr = r0 - 1 + rr;
    cpa16(buf + rr * TILE_RP + col, xc16 + gr * 64 + col, (unsigned)gr < 64u);
  }
}

// ============================================================================
// FUSED kernel, L1-traffic-reduced: conv tiles are 4 outch x 8 px (halves the
// ocp-group row re-reads), halos come from neighbor lanes via shfl (no scalar
// LDS), and the KB passes use float4 / bf16x4 vector loads.
// ============================================================================
__global__ void __launch_bounds__(512, 2) fused_kernel(
    const float* __restrict__ x,
    const float* __restrict__ w1, const float* __restrict__ b1,
    const float* __restrict__ wh, const float* __restrict__ bh,
    const float* __restrict__ ww, const float* __restrict__ bw,
    const float* __restrict__ w3, const float* __restrict__ b3,
    const float* __restrict__ gnw, const float* __restrict__ gnb,
    float* __restrict__ out)
{
  extern __shared__ float sm[];
  float* tile  = sm + OFF_T;
  float* s_w3d = sm + OFF_W3D;
  float* s_rs  = sm + OFF_RS;         // [16][64] row sums
  // overlays inside tile region (used after last conv sync)
  float* s_xw = sm + OFF_T + 1024;    // [16][64] col sums
  float* s_y  = sm + OFF_T + 2048;    // [16][128]
  float* s_W  = sm + OFF_T + 4096;    // W1(256) Wh(256) Ww(256)
  float* s_bb = sm + OFF_T + 4864;    // b1(16) bh(16) bw(16)
  float* s_s  = sm + OFF_T + 5120;    // [4096] KB logits/exp

  __shared__ float s_b3[16], schmax3[16], schsum3[16];
  __shared__ float s_ah[1024], s_aw[1024];
  __shared__ float s_k[16], s_e2[16], s_m3[16], s_w2[16], s_w3v[16];
  __shared__ float schsum1[16], schsq1[16], schmax1[16], schmin1[16];
  __shared__ float s_r1[16];
  __shared__ float s_mu, s_rsd, s_smax, s_sinv;

  const int t = threadIdx.x, warp = t >> 5, lane = t & 31;
  const int g = blockIdx.x;
  const float* xg = x + (size_t)g * CG * HW;
  const float* xch = xg + warp * HW;   // this warp's channel

  // ---- init: guard, pads, weights ----
  if (t < 16) { sm[t] = 0.f; s_b3[t] = b3[t]; schmax3[t] = 0.f; schsum3[t] = 0.f; }
  if (t < 288) {
    float* row = tile + t * TILE_RP;
    row[64] = 0.f; row[65] = 0.f; row[66] = 0.f; row[67] = 0.f;
  }
  for (int i = t; i < 2304; i += 512) {
    float v = w3[i];
    s_w3d[2 * i] = v; s_w3d[2 * i + 1] = v;
  }

  // ======================= KA phase: conv + pooled stats ====================
  float4 csum4 = make_float4(0.f, 0.f, 0.f, 0.f);
  const int ocp = t >> 7;                       // 0..3 -> oc = ocp*4 + j
  const int ti = t & 127, rr = ti >> 3, cb = ti & 7;  // row 0..15, 8-px blk 0..7
  float s3a[4] = {0.f, 0.f, 0.f, 0.f};
  float m3a[4] = {0.f, 0.f, 0.f, 0.f};
  const ull* w3du = reinterpret_cast<const ull*>(s_w3d);
  const int half = lane >> 4, col4 = (lane & 15) * 4;

  #pragma unroll 1
  for (int s = 0; s < 4; s++) {
    const int r0 = s * 16;
    issue_strip(tile + warp * TILE_CP, xch, lane, r0);
    cpa_commit();
    cpa_wait<0>();
    __syncthreads();                 // strip visible to all

    // stats: warp == channel, data rows 1..16
    {
      const float* bch = tile + warp * TILE_CP;
      #pragma unroll
      for (int st = 0; st < 8; st++) {
        int b = 1 + st * 2 + half;
        float4 v = *reinterpret_cast<const float4*>(bch + b * TILE_RP + col4);
        csum4.x += v.x; csum4.y += v.y; csum4.z += v.z; csum4.w += v.w;
        float rs = (v.x + v.y) + (v.z + v.w);
        #pragma unroll
        for (int o = 1; o < 16; o <<= 1) rs += __shfl_xor_sync(0xffffffffu, rs, o);
        if ((lane & 15) == 0) s_rs[warp * 64 + r0 + st * 2 + half] = rs;
      }
    }

    // conv: one (4 outch x 8 px) tile per thread; halos via shfl
    {
      ull Ac[4][4];
      #pragma unroll
      for (int j = 0; j < 4; j++)
        #pragma unroll
        for (int p = 0; p < 4; p++) Ac[j][p] = 0ull;
      const float* tb = tile + rr * TILE_RP + cb * 8;
      #pragma unroll 1
      for (int ci = 0; ci < 16; ci++) {
        const float* tcb = tb + ci * TILE_CP;
        const ull* wp = w3du + (ocp * 4) * 144 + ci * 9;
        #pragma unroll
        for (int dr = 0; dr < 3; dr++) {
          const float* base = tcb + dr * TILE_RP;
          const float4 q0 = *reinterpret_cast<const float4*>(base);
          const float4 q1 = *reinterpret_cast<const float4*>(base + 4);
          float lft = __shfl_up_sync(0xffffffffu, q1.w, 1);
          if (cb == 0) lft = 0.f;              // image col 0: left halo = 0
          float rgt = __shfl_down_sync(0xffffffffu, q0.x, 1);
          if (cb == 7) rgt = 0.f;              // image col 63: right halo = 0
          ull E0 = pk2(q0.x, q0.y), E1 = pk2(q0.z, q0.w);
          ull E2 = pk2(q1.x, q1.y), E3 = pk2(q1.z, q1.w);
          ull O0 = pk2(lft,  q0.x), O1 = pk2(q0.y, q0.z);
          ull O2 = pk2(q0.w, q1.x), O3 = pk2(q1.y, q1.z);
          ull O4 = pk2(q1.w, rgt);
          #pragma unroll
          for (int j = 0; j < 4; j++) {
            ull u0 = wp[j * 144 + dr * 3];
            ull u1 = wp[j * 144 + dr * 3 + 1];
            ull u2 = wp[j * 144 + dr * 3 + 2];
            fma2(Ac[j][0], u0, O0); fma2(Ac[j][0], u1, E0); fma2(Ac[j][0], u2, O1);
            fma2(Ac[j][1], u0, O1); fma2(Ac[j][1], u1, E1); fma2(Ac[j][1], u2, O2);
            fma2(Ac[j][2], u0, O2); fma2(Ac[j][2], u1, E2); fma2(Ac[j][2], u2, O3);
            fma2(Ac[j][3], u0, O3); fma2(Ac[j][3], u1, E3); fma2(Ac[j][3], u2, O4);
          }
        }
      }
      int grow = r0 + rr;
      #pragma unroll
      for (int j = 0; j < 4; j++) {
        int oc = ocp * 4 + j;
        float bz = s_b3[oc];
        uint32_t pk[4];
        #pragma unroll
        for (int p = 0; p < 4; p++) {
          float2 f = upk2(Ac[j][p]);
          float v0 = fmaxf(f.x + bz, 0.f);
          float v1 = fmaxf(f.y + bz, 0.f);
          s3a[j] += v0 + v1;
          m3a[j] = fmaxf(m3a[j], fmaxf(v0, v1));
          __nv_bfloat162 h = __floats2bfloat162_rn(v0, v1);
          pk[p] = *reinterpret_cast<uint32_t*>(&h);
        }
        __nv_bfloat16* o = g_x3 + ((size_t)g * CG + oc) * HW + grow * 64 + cb * 8;
        *reinterpret_cast<uint4*>(o) = make_uint4(pk[0], pk[1], pk[2], pk[3]);
      }
    }
    __syncthreads();                 // done reading tile before refill
  }

  // ---- fold col sums, x3 stats (warp-reduce then lane0 atomics) ------------
  csum4.x += __shfl_xor_sync(0xffffffffu, csum4.x, 16);
  csum4.y += __shfl_xor_sync(0xffffffffu, csum4.y, 16);
  csum4.z += __shfl_xor_sync(0xffffffffu, csum4.z, 16);
  csum4.w += __shfl_xor_sync(0xffffffffu, csum4.w, 16);
  if (lane < 16) {
    float* d = s_xw + warp * 64 + lane * 4;
    d[0] = csum4.x; d[1] = csum4.y; d[2] = csum4.z; d[3] = csum4.w;
  }
  #pragma unroll
  for (int j = 0; j < 4; j++) {
    s3a[j] = wsum(s3a[j]);
    m3a[j] = wmax(m3a[j]);
    if (lane == 0) {
      atomicAdd(&schsum3[ocp * 4 + j], s3a[j]);
      atomicMax(reinterpret_cast<int*>(&schmax3[ocp * 4 + j]),
                __float_as_int(m3a[j]));   // relu >= 0
    }
  }
  if (t < 256) { s_W[t] = w1[t]; s_W[256 + t] = wh[t]; s_W[512 + t] = ww[t]; }
  if (t < 16) { s_bb[t] = b1[t]; s_bb[16 + t] = bh[t]; s_bb[32 + t] = bw[t]; }
  __syncthreads();

  // y = relu(W1 @ [xh;xw] + b1)
  if (t < 128) {
    float in[16];
    #pragma unroll
    for (int i = 0; i < 16; i++) {
      float raw = (t < 64) ? s_rs[i * 64 + t] : s_xw[i * 64 + (t - 64)];
      in[i] = raw * (1.f / 64.f);
    }
    #pragma unroll
    for (int o = 0; o < 16; o++) {
      float acc = s_bb[o];
      #pragma unroll
      for (int i = 0; i < 16; i++) acc = fmaf(s_W[o * 16 + i], in[i], acc);
      s_y[o * 128 + t] = fmaxf(acc, 0.f);
    }
  }
  __syncthreads();
  // a_h, a_w -> smem
  if (t < 128) {
    const int hf = t >> 6, cc = t & 63;
    const float* Wm = s_W + 256 + hf * 256;
    const float* bm = s_bb + 16 + hf * 16;
    float in[16];
    #pragma unroll
    for (int i = 0; i < 16; i++) in[i] = s_y[i * 128 + t];
    float* dst = hf ? s_aw : s_ah;
    #pragma unroll
    for (int o = 0; o < 16; o++) {
      float acc = bm[o];
      #pragma unroll
      for (int i = 0; i < 16; i++) acc = fmaf(Wm[o * 16 + i], in[i], acc);
      dst[o * 64 + cc] = 1.f / (1.f + __expf(-acc));
    }
  }
  __syncthreads();

  // ======================= KB phase: attention ==============================
  // ---- pass 0: x1 statistics (warp == channel; float4) ----
  {
    const int c = warp;
    const float* xc = xg + c * HW;
    const float* awp = s_aw + c * 64 + ((lane * 4) & 63);
    float aw0 = awp[0], aw1 = awp[1], aw2 = awp[2], aw3 = awp[3];
    const float* ahc = s_ah + c * 64;
    float sum = 0.f, sq = 0.f, mx = -1e30f, mn = 1e30f;
    #pragma unroll 4
    for (int m = 0; m < 32; m++) {
      int l = m * 128 + lane * 4;
      float4 xv = *reinterpret_cast<const float4*>(xc + l);
      float a = ahc[m * 2 + half];
      float v0 = xv.x * a * aw0, v1 = xv.y * a * aw1;
      float v2 = xv.z * a * aw2, v3 = xv.w * a * aw3;
      sum += (v0 + v1) + (v2 + v3);
      sq += (v0 * v0 + v1 * v1) + (v2 * v2 + v3 * v3);
      mx = fmaxf(mx, fmaxf(fmaxf(v0, v1), fmaxf(v2, v3)));
      mn = fminf(mn, fminf(fminf(v0, v1), fminf(v2, v3)));
    }
    sum = wsum(sum); sq = wsum(sq); mx = wmax(mx); mn = wmin(mn);
    if (lane == 0) { schsum1[c] = sum; schsq1[c] = sq; schmax1[c] = mx; schmin1[c] = mn; }
  }
  __syncthreads();
  if (t == 0) {
    float a = 0.f, bq = 0.f;
    #pragma unroll
    for (int i = 0; i < 16; i++) { a += schsum1[i]; bq += schsq1[i]; }
    float mu = a * (1.f / 65536.f);
    float var = bq * (1.f / 65536.f) - mu * mu;
    s_mu = mu; s_rsd = rsqrtf(var + 1e-5f);
  }
  __syncthreads();
  if (t < 16) {
    int c = t;
    float k = s_rsd * gnw[c];
    float d = gnb[c] - s_mu * k;
    float mx1 = (k >= 0.f) ? schmax1[c] : schmin1[c];
    float max2 = mx1 * k + d;
    s_k[c]  = k;
    s_e2[c] = d - max2;
    s_m3[c] = schmax3[c];
    s_w2[c] = schsum3[c] * (1.f / 4096.f);           // V3 (÷ Z2 below)
    s_w3v[c] = schsum1[c] * (1.f / 4096.f) * k + d;  // V2 (÷ Z3 below)
  }
  __syncthreads();

  // ---- pass 1: per-channel Z2, Z3 (float4 / bf16x4) ----
  {
    const int c = warp;
    float k = s_k[c], e2 = s_e2[c], m3 = s_m3[c];
    const float* xc = xg + c * HW;
    const __nv_bfloat16* x3c = g_x3 + ((size_t)g * CG + c) * HW;
    const float* awp = s_aw + c * 64 + ((lane * 4) & 63);
    float aw0 = awp[0], aw1 = awp[1], aw2 = awp[2], aw3 = awp[3];
    const float* ahc = s_ah + c * 64;
    float z2 = 0.f, z3 = 0.f;
    #pragma unroll 4
    for (int m = 0; m < 32; m++) {
      int l = m * 128 + lane * 4;
      float4 xv = *reinterpret_cast<const float4*>(xc + l);
      uint2 hq = *reinterpret_cast<const uint2*>(x3c + l);
      __nv_bfloat162 h0 = *reinterpret_cast<__nv_bfloat162*>(&hq.x);
      __nv_bfloat162 h1 = *reinterpret_cast<__nv_bfloat162*>(&hq.y);
      float a = ahc[m * 2 + half];
      z2 += __expf(fmaf(xv.x * a * aw0, k, e2)) + __expf(fmaf(xv.y * a * aw1, k, e2))
          + __expf(fmaf(xv.z * a * aw2, k, e2)) + __expf(fmaf(xv.w * a * aw3, k, e2));
      z3 += __expf(__bfloat162float(h0.x) - m3) + __expf(__bfloat162float(h0.y) - m3)
          + __expf(__bfloat162float(h1.x) - m3) + __expf(__bfloat162float(h1.y) - m3);
    }
    z2 = wsum(z2); z3 = wsum(z3);
    if (lane == 0) { s_w3v[c] = s_w3v[c] / z3; s_w2[c] = s_w2[c] / z2; }
  }
  __syncthreads();

  // ---- pass 2: s logits, 2 px per thread ----
  const __nv_bfloat16* x3g = g_x3 + (size_t)g * CG * HW;
  float lmax = -1e30f;
  #pragma unroll 1
  for (int rep = 0; rep < 4; rep++) {
    int l0 = (t + rep * 512) * 2;
    int i = l0 >> 6, j = l0 & 63;
    float ax = 0.f, ay = 0.f;
    #pragma unroll
    for (int c = 0; c < 16; c++) {
      float2 xv = *reinterpret_cast<const float2*>(xg + c * HW + l0);
      __nv_bfloat162 x3v = *reinterpret_cast<const __nv_bfloat162*>(x3g + c * HW + l0);
      float ah = s_ah[c * 64 + i];
      float x1x = xv.x * ah * s_aw[c * 64 + j];
      float x1y = xv.y * ah * s_aw[c * 64 + j + 1];
      ax += s_w2[c] * __expf(fmaf(x1x, s_k[c], s_e2[c]));
      ay += s_w2[c] * __expf(fmaf(x1y, s_k[c], s_e2[c]));
      ax += s_w3v[c] * __expf(__bfloat162float(x3v.x) - s_m3[c]);
      ay += s_w3v[c] * __expf(__bfloat162float(x3v.y) - s_m3[c]);
    }
    s_s[l0] = ax; s_s[l0 + 1] = ay;
    lmax = fmaxf(lmax, fmaxf(ax, ay));
  }
  lmax = wmax(lmax);
  if (lane == 0) s_r1[warp] = lmax;
  __syncthreads();
  if (t == 0) {
    float m = -1e30f;
    #pragma unroll
    for (int i = 0; i < 16; i++) m = fmaxf(m, s_r1[i]);
    s_smax = m;
  }
  __syncthreads();
  float lsum = 0.f;
  {
    float smax = s_smax;
    #pragma unroll
    for (int rep = 0; rep < 2; rep++) {
      int l0 = (t + rep * 512) * 4;
      float4 sv = *reinterpret_cast<const float4*>(&s_s[l0]);
      float e0 = __expf(sv.x - smax), e1 = __expf(sv.y - smax);
      float e2v = __expf(sv.z - smax), e3 = __expf(sv.w - smax);
      *reinterpret_cast<float4*>(&s_s[l0]) = make_float4(e0, e1, e2v, e3);
      lsum += (e0 + e1) + (e2v + e3);
    }
  }
  lsum = wsum(lsum);
  if (lane == 0) s_r1[warp] = lsum;
  __syncthreads();
  if (t == 0) {
    float a = 0.f;
    #pragma unroll
    for (int i = 0; i < 16; i++) a += s_r1[i];
    s_sinv = 1.f / a;
  }
  __syncthreads();

  // ---- pass 3: out = x * (e * sinv), float4 ----
  float* og = out + (size_t)g * CG * HW;
  float sinv = s_sinv;
  #pragma unroll 1
  for (int c = 0; c < 16; c++) {
    #pragma unroll
    for (int rep = 0; rep < 2; rep++) {
      int l0 = (t + rep * 512) * 4;
      float4 xv = *reinterpret_cast<const float4*>(xg + c * HW + l0);
      float4 sv = *reinterpret_cast<const float4*>(&s_s[l0]);
      float4 ov;
      ov.x = xv.x * (sv.x * sinv);
      ov.y = xv.y * (sv.y * sinv);
      ov.z = xv.z * (sv.z * sinv);
      ov.w = xv.w * (sv.w * sinv);
      *reinterpret_cast<float4*>(og + c * HW + l0) = ov;
    }
  }
}

// ---------------------------------------------------------------------------
extern "C" void kernel_launch(void* const* d_in, const int* in_sizes, int n_in,
                              void* d_out, int out_size)
{
  const float* x   = (const float*)d_in[0];
  const float* w1  = (const float*)d_in[1];
  const float* b1  = (const float*)d_in[2];
  const float* wh  = (const float*)d_in[3];
  const float* bh  = (const float*)d_in[4];
  const float* ww  = (const float*)d_in[5];
  const float* bw  = (const float*)d_in[6];
  const float* w3  = (const float*)d_in[7];
  const float* b3  = (const float*)d_in[8];
  const float* gnw = (const float*)d_in[9];
  const float* gnb = (const float*)d_in[10];

  cudaFuncSetAttribute(fused_kernel, cudaFuncAttributeMaxDynamicSharedMemorySize,
                       SM_TOTF * (int)sizeof(float));
  fused_kernel<<<NG, 512, SM_TOTF * sizeof(float)>>>(
      x, w1, b1, wh, bh, ww, bw, w3, b3, gnw, gnb, (float*)d_out);
}